// round 5
// baseline (speedup 1.0000x reference)
#include <cuda_runtime.h>
#include <cstdint>

#define NBLK   148

// ---- node gemm (f32x2, exact) ----
#define TPB_G   512
#define NWARP_G 16
#define RB      8
#define GEMM_SMEM (64*1024 + NWARP_G*RB*128*4)   // 128 KB

// ---- edge mma kernel ----
#define TPB_E   256
#define WB_FLOATS (8*16*32*4)          // 16384 floats = 64 KB (W2 frag layout)
#define TA_STRIDE 260                  // floats per kstep block (16B-aligned rows)
#define TA_WARP   (16*TA_STRIDE)       // 4160 floats per warp
#define EDGE_SMEM ((WB_FLOATS + 8*TA_WARP) * 4)  // 198656 B

// Scratch (device globals: allocation-free rule)
__device__ float g_h  [50000 * 128];
__device__ float g_A  [50000 * 128];
__device__ float g_B  [50000 * 128];
__device__ float g_agg[50000 * 128];
__device__ float g_pool[64 * 128];
__device__ float g_cnt [64];
__device__ int   g_deg [50000];

typedef unsigned long long u64;

__device__ __forceinline__ float4 relu4(float4 v) {
    v.x = fmaxf(v.x, 0.f); v.y = fmaxf(v.y, 0.f);
    v.z = fmaxf(v.z, 0.f); v.w = fmaxf(v.w, 0.f);
    return v;
}

// ======================= tf32 mma helpers =======================
__device__ __forceinline__ uint32_t f2tf32(float f) {
    uint32_t r; asm("cvt.rna.tf32.f32 %0, %1;" : "=r"(r) : "f"(f)); return r;
}
__device__ __forceinline__ void mma8(float4 &d, uint32_t a0, uint32_t a1,
                                     uint32_t a2, uint32_t a3,
                                     uint32_t b0, uint32_t b1) {
    asm volatile("mma.sync.aligned.m16n8k8.row.col.f32.tf32.tf32.f32 "
        "{%0,%1,%2,%3}, {%4,%5,%6,%7}, {%8,%9}, {%0,%1,%2,%3};"
        : "+f"(d.x), "+f"(d.y), "+f"(d.z), "+f"(d.w)
        : "r"(a0), "r"(a1), "r"(a2), "r"(a3), "r"(b0), "r"(b1));
}
// Split float4 (tile order: .x=a0, .z=a1, .y=a2, .w=a3) into tf32 hi + lo
__device__ __forceinline__ void split4(float4 v, uint32_t h[4], uint32_t l[4]) {
    float f0 = v.x, f1 = v.z, f2 = v.y, f3 = v.w;
    h[0] = f2tf32(f0); l[0] = f2tf32(f0 - __uint_as_float(h[0]));
    h[1] = f2tf32(f1); l[1] = f2tf32(f1 - __uint_as_float(h[1]));
    h[2] = f2tf32(f2); l[2] = f2tf32(f2 - __uint_as_float(h[2]));
    h[3] = f2tf32(f3); l[3] = f2tf32(f3 - __uint_as_float(h[3]));
}

// ======================= f32x2 node GEMM =======================
__device__ __forceinline__ void ffma2(u64 &acc, u64 a, u64 b) {
    asm("fma.rn.f32x2 %0, %1, %2, %0;" : "+l"(acc) : "l"(a), "l"(b));
}
__device__ __forceinline__ float pairsum(u64 p) {
    float lo, hi;
    asm("mov.b64 {%0, %1}, %2;" : "=f"(lo), "=f"(hi) : "l"(p));
    return lo + hi;
}
__device__ __forceinline__ u64 packf2(float lo, float hi) {
    u64 r;
    asm("mov.b64 %0, {%1, %2};" : "=l"(r) : "f"(lo), "f"(hi));
    return r;
}

__device__ __forceinline__ void stage_w_pairs(u64* Wp, const float* __restrict__ W) {
    for (int idx = threadIdx.x; idx < 64 * 128; idx += TPB_G) {
        int m = idx >> 7, n = idx & 127;
        Wp[idx] = packf2(W[(2 * m) * 128 + n], W[(2 * m + 1) * 128 + n]);
    }
}

__device__ __forceinline__ void mm_tile(u64 acc[RB][4], const float* tb, const u64* Wp, int lane) {
    #pragma unroll 2
    for (int mm = 0; mm < 32; mm++) {
        const u64* r0 = Wp + (2 * mm) * 128;
        const u64* r1 = Wp + (2 * mm + 1) * 128;
        ulonglong2 wa0 = ((const ulonglong2*)r0)[lane];
        ulonglong2 wb0 = ((const ulonglong2*)r0)[lane + 32];
        ulonglong2 wa1 = ((const ulonglong2*)r1)[lane];
        ulonglong2 wb1 = ((const ulonglong2*)r1)[lane + 32];
        #pragma unroll
        for (int e = 0; e < RB; e++) {
            ulonglong2 xp = ((const ulonglong2*)(tb + e * 128))[mm];
            ffma2(acc[e][0], xp.x, wa0.x);
            ffma2(acc[e][1], xp.x, wa0.y);
            ffma2(acc[e][2], xp.x, wb0.x);
            ffma2(acc[e][3], xp.x, wb0.y);
            ffma2(acc[e][0], xp.y, wa1.x);
            ffma2(acc[e][1], xp.y, wa1.y);
            ffma2(acc[e][2], xp.y, wb1.x);
            ffma2(acc[e][3], xp.y, wb1.y);
        }
    }
}

template <bool RELU_IN>
__global__ void __launch_bounds__(TPB_G, 1)
gemm128_kernel(const float* __restrict__ X, const float* __restrict__ W,
               const float* __restrict__ bias, float* __restrict__ Y, int nrows)
{
    extern __shared__ float sm[];
    u64*   Wp = (u64*)sm;
    float* xb = sm + 64 * 128 * 2;

    stage_w_pairs(Wp, W);
    __syncthreads();

    const int warp = threadIdx.x >> 5, lane = threadIdx.x & 31;
    float* tb = xb + warp * RB * 128;

    float2 b01 = make_float2(0.f, 0.f), b23 = make_float2(0.f, 0.f);
    if (bias) {
        b01 = ((const float2*)bias)[lane];
        b23 = ((const float2*)bias)[lane + 32];
    }

    const int gwarp  = blockIdx.x * NWARP_G + warp;
    const int nwarps = gridDim.x * NWARP_G;
    const int ntasks = (nrows + RB - 1) / RB;

    for (int task = gwarp; task < ntasks; task += nwarps) {
        const int row0 = task * RB;
        #pragma unroll
        for (int e = 0; e < RB; e++) {
            int r = row0 + e;
            float4 v = make_float4(0.f, 0.f, 0.f, 0.f);
            if (r < nrows) v = ((const float4*)(X + (size_t)r * 128))[lane];
            if (RELU_IN) v = relu4(v);
            ((float4*)(tb + e * 128))[lane] = v;
        }
        __syncwarp();

        u64 acc[RB][4];
        #pragma unroll
        for (int e = 0; e < RB; e++)
            acc[e][0] = acc[e][1] = acc[e][2] = acc[e][3] = 0ull;

        mm_tile(acc, tb, Wp, lane);

        #pragma unroll
        for (int e = 0; e < RB; e++) {
            int r = row0 + e;
            if (r < nrows) {
                float2 o01 = make_float2(pairsum(acc[e][0]) + b01.x, pairsum(acc[e][1]) + b01.y);
                float2 o23 = make_float2(pairsum(acc[e][2]) + b23.x, pairsum(acc[e][3]) + b23.y);
                ((float2*)(Y + (size_t)r * 128))[lane]      = o01;
                ((float2*)(Y + (size_t)r * 128))[lane + 32] = o23;
            }
        }
        __syncwarp();
    }
}

// ======================= edge kernel: tf32 mma.sync =======================
// Per warp-pair: 32 edges. Warp covers m32 x n64 x k128, 2-pass hi/lo on
// activations (W2 truncated to tf32). D scattered to agg[dst] via atomics.
__global__ void __launch_bounds__(TPB_E, 1)
edge_mma_kernel(const float* __restrict__ A, const float* __restrict__ Bm,
                const int* __restrict__ src, const int* __restrict__ dst,
                const float* __restrict__ W2, float* __restrict__ agg,
                int Ereal, int Etot, int ntasks)
{
    extern __shared__ float sm[];
    float* Wb = sm;   // [8 kk2][16 nb][32 lane][4] tf32 bit patterns
    const int tid = threadIdx.x, wid = tid >> 5, lane = tid & 31;
    float* ta = sm + WB_FLOATS + wid * TA_WARP;

    // Stage W2 into B-fragment layout (tf32-rounded), once.
    for (int i = tid; i < 4096; i += TPB_E) {
        int kk2 = i >> 9, rem = i & 511, nb = rem >> 5, ln = rem & 31;
        int n = nb * 8 + (ln >> 2), k = kk2 * 16 + (ln & 3);
        uint4 v;
        v.x = f2tf32(W2[(k     ) * 128 + n]);
        v.y = f2tf32(W2[(k +  4) * 128 + n]);
        v.z = f2tf32(W2[(k +  8) * 128 + n]);
        v.w = f2tf32(W2[(k + 12) * 128 + n]);
        ((uint4*)Wb)[i] = v;
    }
    __syncthreads();

    const int pair   = (blockIdx.x << 2) | (wid >> 1);
    const int npairs = gridDim.x << 2;
    const int nhalf  = wid & 1;
    const int ks     = lane >> 1;                         // store-side kstep
    const int sbase  = ks * TA_STRIDE + (lane & 1);       // + mf*128 + rhigh*2 + klm*4

    for (int task = pair; task < ntasks; task += npairs) {
        const int e0 = task * 32;
        __syncwarp();

        // ---- gather 32 edges into fragment-layout tile ----
        #pragma unroll 4
        for (int e = 0; e < 32; e++) {
            int idx = e0 + e;
            float4 t = make_float4(0.f, 0.f, 0.f, 0.f);
            if (idx < Etot) {
                int s, d;
                if (idx < Ereal) { s = __ldg(src + idx); d = __ldg(dst + idx); }
                else             { s = d = idx - Ereal; }
                float4 a = ((const float4*)(A  + (size_t)d * 128))[lane];
                float4 b = ((const float4*)(Bm + (size_t)s * 128))[lane];
                t = relu4(make_float4(a.x + b.x, a.y + b.y, a.z + b.z, a.w + b.w));
            }
            float* p = ta + sbase + ((e >> 4) & 1) * 128 + ((e >> 3) & 1) * 2 + (e & 7) * 16;
            p[0]  = t.x;
            p[4]  = t.y;
            p[8]  = t.z;
            p[12] = t.w;
        }
        __syncwarp();

        // ---- mma: m32 x n64 x k128, hi+lo passes ----
        float4 acc[2][8];
        #pragma unroll
        for (int mf = 0; mf < 2; mf++)
            #pragma unroll
            for (int nb = 0; nb < 8; nb++)
                acc[mf][nb] = make_float4(0.f, 0.f, 0.f, 0.f);

        #pragma unroll
        for (int kk2 = 0; kk2 < 8; kk2++) {
            float4 ve0 = *(float4*)(ta + (2 * kk2    ) * TA_STRIDE +       lane * 4);
            float4 ve1 = *(float4*)(ta + (2 * kk2    ) * TA_STRIDE + 128 + lane * 4);
            float4 vo0 = *(float4*)(ta + (2 * kk2 + 1) * TA_STRIDE +       lane * 4);
            float4 vo1 = *(float4*)(ta + (2 * kk2 + 1) * TA_STRIDE + 128 + lane * 4);
            uint32_t he0[4], le0[4], he1[4], le1[4], ho0[4], lo0[4], ho1[4], lo1[4];
            split4(ve0, he0, le0);
            split4(ve1, he1, le1);
            split4(vo0, ho0, lo0);
            split4(vo1, ho1, lo1);

            const uint4* wrow = ((const uint4*)Wb) + (kk2 * 16 + nhalf * 8) * 32 + lane;
            #pragma unroll
            for (int nb = 0; nb < 8; nb++) {
                uint4 B = wrow[nb * 32];
                mma8(acc[0][nb], he0[0], he0[1], he0[2], he0[3], B.x, B.y);
                mma8(acc[0][nb], le0[0], le0[1], le0[2], le0[3], B.x, B.y);
                mma8(acc[0][nb], ho0[0], ho0[1], ho0[2], ho0[3], B.z, B.w);
                mma8(acc[0][nb], lo0[0], lo0[1], lo0[2], lo0[3], B.z, B.w);
                mma8(acc[1][nb], he1[0], he1[1], he1[2], he1[3], B.x, B.y);
                mma8(acc[1][nb], le1[0], le1[1], le1[2], le1[3], B.x, B.y);
                mma8(acc[1][nb], ho1[0], ho1[1], ho1[2], ho1[3], B.z, B.w);
                mma8(acc[1][nb], lo1[0], lo1[1], lo1[2], lo1[3], B.z, B.w);
            }
        }

        // ---- scatter to agg[dst] ----
        int r0 = e0 + (lane >> 2);
        int dd[4];
        #pragma unroll
        for (int q = 0; q < 4; q++) {
            int idx = r0 + q * 8;
            if (idx >= Etot)      dd[q] = -1;
            else if (idx < Ereal) dd[q] = __ldg(dst + idx);
            else                  dd[q] = idx - Ereal;
        }
        const int colb = nhalf * 64 + 2 * (lane & 3);
        #pragma unroll
        for (int mf = 0; mf < 2; mf++) {
            int dl = dd[mf * 2], dh = dd[mf * 2 + 1];
            #pragma unroll
            for (int nb = 0; nb < 8; nb++) {
                float4 v = acc[mf][nb];
                int c = colb + nb * 8;
                if (dl >= 0) {
                    atomicAdd(agg + (size_t)dl * 128 + c,     v.x);
                    atomicAdd(agg + (size_t)dl * 128 + c + 1, v.y);
                }
                if (dh >= 0) {
                    atomicAdd(agg + (size_t)dh * 128 + c,     v.z);
                    atomicAdd(agg + (size_t)dh * 128 + c + 1, v.w);
                }
            }
        }
    }
}

// ======================= small kernels =======================
__global__ void deg_kernel(const int* __restrict__ dst, int* __restrict__ deg, int E) {
    int i = blockIdx.x * blockDim.x + threadIdx.x;
    if (i < E) atomicAdd(&deg[dst[i]], 1);
}

// agg[n][c] = (deg[n]+1) * b2[c]   (folds per-message bias into target init)
__global__ void init_agg_kernel(float* __restrict__ agg, const int* __restrict__ deg,
                                const float* __restrict__ b2, int n) {
    int id = blockIdx.x * blockDim.x + threadIdx.x;
    if (id < n * 32) {
        int node = id >> 5, c = id & 31;
        float s = (float)(deg[node] + 1);
        float4 b = ((const float4*)b2)[c];
        ((float4*)(agg + (size_t)node * 128))[c] = make_float4(s * b.x, s * b.y, s * b.z, s * b.w);
    }
}

__global__ void pool_kernel(const float* __restrict__ agg, const int* __restrict__ batch,
                            float* __restrict__ pool, float* __restrict__ cnt, int n)
{
    int gw   = (blockIdx.x * blockDim.x + threadIdx.x) >> 5;
    int lane = threadIdx.x & 31;
    int nw   = (gridDim.x * blockDim.x) >> 5;
    for (int node = gw; node < n; node += nw) {
        int g = batch[node];
        float4 v = relu4(((const float4*)(agg + (size_t)node * 128))[lane]);
        float* p = pool + (size_t)g * 128 + lane * 4;
        atomicAdd(p + 0, v.x); atomicAdd(p + 1, v.y);
        atomicAdd(p + 2, v.z); atomicAdd(p + 3, v.w);
        if (lane == 0) atomicAdd(&cnt[g], 1.f);
    }
}

__global__ void final_kernel(const float* __restrict__ pool, const float* __restrict__ cnt,
                             const float* __restrict__ W, const float* __restrict__ b,
                             float* __restrict__ out)
{
    __shared__ float p[128];
    int g = blockIdx.x;
    float c = fmaxf(cnt[g], 1.f);
    for (int j = threadIdx.x; j < 128; j += blockDim.x)
        p[j] = pool[(size_t)g * 128 + j] / c;
    __syncthreads();
    int o = threadIdx.x;
    float s = b[o];
    #pragma unroll 4
    for (int j = 0; j < 128; j++) s += p[j] * W[j * 64 + o];
    out[(size_t)g * 64 + o] = s;
}

// ======================= launch =======================
extern "C" void kernel_launch(void* const* d_in, const int* in_sizes, int n_in,
                              void* d_out, int out_size)
{
    const float* x     = (const float*)d_in[0];
    const int*   ei    = (const int*)  d_in[1];
    const int*   batch = (const int*)  d_in[3];
    const int N = in_sizes[0] / 128;
    const int E = in_sizes[1] / 2;
    const int* src = ei;
    const int* dst = ei + E;

    const float* lin_w[3] = { (const float*)d_in[4],  (const float*)d_in[10], (const float*)d_in[16] };
    const float* lin_b[3] = { (const float*)d_in[5],  (const float*)d_in[11], (const float*)d_in[17] };
    const float* w1[3]    = { (const float*)d_in[6],  (const float*)d_in[12], (const float*)d_in[18] };
    const float* b1[3]    = { (const float*)d_in[7],  (const float*)d_in[13], (const float*)d_in[19] };
    const float* w2[3]    = { (const float*)d_in[8],  (const float*)d_in[14], (const float*)d_in[20] };
    const float* b2[3]    = { (const float*)d_in[9],  (const float*)d_in[15], (const float*)d_in[21] };
    const float* out_w    = (const float*)d_in[22];
    const float* out_b    = (const float*)d_in[23];
    float* out = (float*)d_out;

    float *h_, *A_, *B_, *agg_, *pool_, *cnt_;
    int* deg_;
    cudaGetSymbolAddress((void**)&h_,    g_h);
    cudaGetSymbolAddress((void**)&A_,    g_A);
    cudaGetSymbolAddress((void**)&B_,    g_B);
    cudaGetSymbolAddress((void**)&agg_,  g_agg);
    cudaGetSymbolAddress((void**)&pool_, g_pool);
    cudaGetSymbolAddress((void**)&cnt_,  g_cnt);
    cudaGetSymbolAddress((void**)&deg_,  g_deg);

    cudaFuncSetAttribute((const void*)gemm128_kernel<false>,
                         cudaFuncAttributeMaxDynamicSharedMemorySize, GEMM_SMEM);
    cudaFuncSetAttribute((const void*)gemm128_kernel<true>,
                         cudaFuncAttributeMaxDynamicSharedMemorySize, GEMM_SMEM);
    cudaFuncSetAttribute((const void*)edge_mma_kernel,
                         cudaFuncAttributeMaxDynamicSharedMemorySize, EDGE_SMEM);

    const int Etot   = E + N;
    const int ntasks = (Etot + 31) / 32;
    const int G = out_size / 64;

    cudaMemsetAsync(deg_, 0, (size_t)N * sizeof(int));
    deg_kernel<<<(E + 255) / 256, 256>>>(dst, deg_, E);

    for (int l = 0; l < 3; l++) {
        const float* X = (l == 0) ? x : agg_;
        if (l == 0)
            gemm128_kernel<false><<<NBLK, TPB_G, GEMM_SMEM>>>(X, lin_w[l], lin_b[l], h_, N);
        else
            gemm128_kernel<true ><<<NBLK, TPB_G, GEMM_SMEM>>>(X, lin_w[l], lin_b[l], h_, N);
        gemm128_kernel<false><<<NBLK, TPB_G, GEMM_SMEM>>>(h_, w1[l],             b1[l],  A_, N);
        gemm128_kernel<false><<<NBLK, TPB_G, GEMM_SMEM>>>(h_, w1[l] + 128 * 128, nullptr, B_, N);
        init_agg_kernel<<<(N * 32 + 255) / 256, 256>>>(agg_, deg_, b2[l], N);
        edge_mma_kernel<<<NBLK, TPB_E, EDGE_SMEM>>>(A_, B_, src, dst, w2[l], agg_, E, Etot, ntasks);
    }

    cudaMemsetAsync(pool_, 0, (size_t)G * 128 * sizeof(float));
    cudaMemsetAsync(cnt_,  0, (size_t)G * sizeof(float));
    pool_kernel<<<256, 256>>>(agg_, batch, pool_, cnt_, N);
    final_kernel<<<G, 64>>>(pool_, cnt_, out_w, out_b, out);
}

// round 6
// speedup vs baseline: 1.6209x; 1.6209x over previous
#include <cuda_runtime.h>
#include <cstdint>

#define NBLK   148

// ---- node gemm (f32x2, exact) ----
#define TPB_G   512
#define NWARP_G 16
#define RB      8
#define GEMM_SMEM (64*1024 + NWARP_G*RB*128*4)   // 128 KB

// ---- edge mma kernel ----
#define TPB_E   512
#define EW_TILE  (16*132)                        // floats per warp tile (16 kk rows x 132)
#define WB_FLOATS (8*16*32*4)                    // 16384 floats = 64 KB (W2 frag layout)
#define EDGE_SMEM ((WB_FLOATS + 16*EW_TILE) * 4) // 64KB + 132KB = 200704 B

// Scratch (device globals: allocation-free rule)
__device__ float g_h  [50000 * 128];
__device__ float g_A  [50000 * 128];
__device__ float g_B  [50000 * 128];
__device__ float g_agg[50000 * 128];
__device__ float g_pool[64 * 128];
__device__ float g_cnt [64];
__device__ int   g_deg [50000];

typedef unsigned long long u64;

__device__ __forceinline__ float4 relu4(float4 v) {
    v.x = fmaxf(v.x, 0.f); v.y = fmaxf(v.y, 0.f);
    v.z = fmaxf(v.z, 0.f); v.w = fmaxf(v.w, 0.f);
    return v;
}

// ======================= tf32 mma helpers =======================
__device__ __forceinline__ uint32_t f2tf32(float f) {
    uint32_t r; asm("cvt.rna.tf32.f32 %0, %1;" : "=r"(r) : "f"(f)); return r;
}
__device__ __forceinline__ void mma8(float4 &d, uint32_t a0, uint32_t a1,
                                     uint32_t a2, uint32_t a3,
                                     uint32_t b0, uint32_t b1) {
    asm volatile("mma.sync.aligned.m16n8k8.row.col.f32.tf32.tf32.f32 "
        "{%0,%1,%2,%3}, {%4,%5,%6,%7}, {%8,%9}, {%0,%1,%2,%3};"
        : "+f"(d.x), "+f"(d.y), "+f"(d.z), "+f"(d.w)
        : "r"(a0), "r"(a1), "r"(a2), "r"(a3), "r"(b0), "r"(b1));
}
// Straight-order split: tile stores fragments as (a0,a1,a2,a3) contiguous.
__device__ __forceinline__ void split4s(float4 v, uint32_t h[4], uint32_t l[4]) {
    h[0] = f2tf32(v.x); l[0] = f2tf32(v.x - __uint_as_float(h[0]));
    h[1] = f2tf32(v.y); l[1] = f2tf32(v.y - __uint_as_float(h[1]));
    h[2] = f2tf32(v.z); l[2] = f2tf32(v.z - __uint_as_float(h[2]));
    h[3] = f2tf32(v.w); l[3] = f2tf32(v.w - __uint_as_float(h[3]));
}
__device__ __forceinline__ void redv2(float* p, float a, float b) {
    asm volatile("red.global.add.v2.f32 [%0], {%1, %2};" :: "l"(p), "f"(a), "f"(b) : "memory");
}

// ======================= f32x2 node GEMM =======================
__device__ __forceinline__ void ffma2(u64 &acc, u64 a, u64 b) {
    asm("fma.rn.f32x2 %0, %1, %2, %0;" : "+l"(acc) : "l"(a), "l"(b));
}
__device__ __forceinline__ float pairsum(u64 p) {
    float lo, hi;
    asm("mov.b64 {%0, %1}, %2;" : "=f"(lo), "=f"(hi) : "l"(p));
    return lo + hi;
}
__device__ __forceinline__ u64 packf2(float lo, float hi) {
    u64 r;
    asm("mov.b64 %0, {%1, %2};" : "=l"(r) : "f"(lo), "f"(hi));
    return r;
}

__device__ __forceinline__ void stage_w_pairs(u64* Wp, const float* __restrict__ W) {
    for (int idx = threadIdx.x; idx < 64 * 128; idx += TPB_G) {
        int m = idx >> 7, n = idx & 127;
        Wp[idx] = packf2(W[(2 * m) * 128 + n], W[(2 * m + 1) * 128 + n]);
    }
}

__device__ __forceinline__ void mm_tile(u64 acc[RB][4], const float* tb, const u64* Wp, int lane) {
    #pragma unroll 2
    for (int mm = 0; mm < 32; mm++) {
        const u64* r0 = Wp + (2 * mm) * 128;
        const u64* r1 = Wp + (2 * mm + 1) * 128;
        ulonglong2 wa0 = ((const ulonglong2*)r0)[lane];
        ulonglong2 wb0 = ((const ulonglong2*)r0)[lane + 32];
        ulonglong2 wa1 = ((const ulonglong2*)r1)[lane];
        ulonglong2 wb1 = ((const ulonglong2*)r1)[lane + 32];
        #pragma unroll
        for (int e = 0; e < RB; e++) {
            ulonglong2 xp = ((const ulonglong2*)(tb + e * 128))[mm];
            ffma2(acc[e][0], xp.x, wa0.x);
            ffma2(acc[e][1], xp.x, wa0.y);
            ffma2(acc[e][2], xp.x, wb0.x);
            ffma2(acc[e][3], xp.x, wb0.y);
            ffma2(acc[e][0], xp.y, wa1.x);
            ffma2(acc[e][1], xp.y, wa1.y);
            ffma2(acc[e][2], xp.y, wb1.x);
            ffma2(acc[e][3], xp.y, wb1.y);
        }
    }
}

template <bool RELU_IN>
__global__ void __launch_bounds__(TPB_G, 1)
gemm128_kernel(const float* __restrict__ X, const float* __restrict__ W,
               const float* __restrict__ bias, float* __restrict__ Y, int nrows)
{
    extern __shared__ float sm[];
    u64*   Wp = (u64*)sm;
    float* xb = sm + 64 * 128 * 2;

    stage_w_pairs(Wp, W);
    __syncthreads();

    const int warp = threadIdx.x >> 5, lane = threadIdx.x & 31;
    float* tb = xb + warp * RB * 128;

    float2 b01 = make_float2(0.f, 0.f), b23 = make_float2(0.f, 0.f);
    if (bias) {
        b01 = ((const float2*)bias)[lane];
        b23 = ((const float2*)bias)[lane + 32];
    }

    const int gwarp  = blockIdx.x * NWARP_G + warp;
    const int nwarps = gridDim.x * NWARP_G;
    const int ntasks = (nrows + RB - 1) / RB;

    for (int task = gwarp; task < ntasks; task += nwarps) {
        const int row0 = task * RB;
        #pragma unroll
        for (int e = 0; e < RB; e++) {
            int r = row0 + e;
            float4 v = make_float4(0.f, 0.f, 0.f, 0.f);
            if (r < nrows) v = ((const float4*)(X + (size_t)r * 128))[lane];
            if (RELU_IN) v = relu4(v);
            ((float4*)(tb + e * 128))[lane] = v;
        }
        __syncwarp();

        u64 acc[RB][4];
        #pragma unroll
        for (int e = 0; e < RB; e++)
            acc[e][0] = acc[e][1] = acc[e][2] = acc[e][3] = 0ull;

        mm_tile(acc, tb, Wp, lane);

        #pragma unroll
        for (int e = 0; e < RB; e++) {
            int r = row0 + e;
            if (r < nrows) {
                float2 o01 = make_float2(pairsum(acc[e][0]) + b01.x, pairsum(acc[e][1]) + b01.y);
                float2 o23 = make_float2(pairsum(acc[e][2]) + b23.x, pairsum(acc[e][3]) + b23.y);
                ((float2*)(Y + (size_t)r * 128))[lane]      = o01;
                ((float2*)(Y + (size_t)r * 128))[lane + 32] = o23;
            }
        }
        __syncwarp();
    }
}

// ======================= edge kernel: tf32 mma.sync, m16 x n128 x k128 per warp =======================
// Each warp owns 16 edges, fully independent. t = relu(A[dst]+B[src]) hi/lo-split;
// D = t @ W2^T accumulated over tf32 MMAs; rows scattered into agg[dst] via red.v2.
__global__ void __launch_bounds__(TPB_E, 1)
edge_mma_kernel(const float* __restrict__ A, const float* __restrict__ Bm,
                const int* __restrict__ src, const int* __restrict__ dst,
                const float* __restrict__ W2, float* __restrict__ agg,
                int Ereal, int Etot, int ntasks)
{
    extern __shared__ float sm[];
    float* Wb = sm;   // [8 kk2][16 nb][32 lane] uint4 tf32 B-fragments
    const int tid = threadIdx.x, wid = tid >> 5, lane = tid & 31;
    float* ta = sm + WB_FLOATS + wid * EW_TILE;

    // Stage W2 (row-major [k][n]) into B-fragment layout, tf32-rounded, once.
    for (int i = tid; i < 4096; i += TPB_E) {
        int kk2 = i >> 9, rem = i & 511, nb = rem >> 5, ln = rem & 31;
        int n = nb * 8 + (ln >> 2), k = kk2 * 16 + (ln & 3);
        uint4 v;
        v.x = f2tf32(W2[(k     ) * 128 + n]);
        v.y = f2tf32(W2[(k +  4) * 128 + n]);
        v.z = f2tf32(W2[(k +  8) * 128 + n]);
        v.w = f2tf32(W2[(k + 12) * 128 + n]);
        ((uint4*)Wb)[i] = v;
    }
    __syncthreads();

    const int gwarp  = blockIdx.x * 16 + wid;
    const int nwarps = gridDim.x * 16;
    // store base: lane provides cols [4L, 4L+3] of each edge row.
    // addr(e, 4L+j0) = (L>>1)*132 + ((e&7)*4 + j0)*4 + (e>>3) + 2*(L&1)
    const int sbase = (lane >> 1) * 132 + 2 * (lane & 1);

    for (int task = gwarp; task < ntasks; task += nwarps) {
        const int e0 = task * 16;
        __syncwarp();

        // ---- gather 16 edges into fragment-layout tile ----
        #pragma unroll 4
        for (int e = 0; e < 16; e++) {
            int idx = e0 + e;
            float4 t = make_float4(0.f, 0.f, 0.f, 0.f);
            if (idx < Etot) {
                int s, d;
                if (idx < Ereal) { s = __ldg(src + idx); d = __ldg(dst + idx); }
                else             { s = d = idx - Ereal; }
                float4 a = ((const float4*)(A  + (size_t)d * 128))[lane];
                float4 b = ((const float4*)(Bm + (size_t)s * 128))[lane];
                t = relu4(make_float4(a.x + b.x, a.y + b.y, a.z + b.z, a.w + b.w));
            }
            float* p = ta + sbase + (e & 7) * 16 + (e >> 3);
            p[0]  = t.x;
            p[4]  = t.y;
            p[8]  = t.z;
            p[12] = t.w;
        }
        __syncwarp();

        // ---- mma: m16 x n128 x k128, hi+lo passes ----
        float4 acc[16];
        #pragma unroll
        for (int nb = 0; nb < 16; nb++) acc[nb] = make_float4(0.f, 0.f, 0.f, 0.f);

        #pragma unroll
        for (int kk2 = 0; kk2 < 8; kk2++) {
            float4 ve = *(float4*)(ta + (2 * kk2    ) * 132 + lane * 4);
            float4 vo = *(float4*)(ta + (2 * kk2 + 1) * 132 + lane * 4);
            uint32_t he[4], le[4], ho[4], lo[4];
            split4s(ve, he, le);
            split4s(vo, ho, lo);

            const uint4* wrow = ((const uint4*)Wb) + kk2 * 512 + lane;
            #pragma unroll
            for (int nb = 0; nb < 16; nb++) {
                uint4 B = wrow[nb * 32];
                mma8(acc[nb], he[0], he[1], he[2], he[3], B.x, B.y);
                mma8(acc[nb], le[0], le[1], le[2], le[3], B.x, B.y);
                mma8(acc[nb], ho[0], ho[1], ho[2], ho[3], B.z, B.w);
                mma8(acc[nb], lo[0], lo[1], lo[2], lo[3], B.z, B.w);
            }
        }

        // ---- scatter to agg[dst]: lane owns rows (lane>>2) and (lane>>2)+8, cols 2*(lane&3)+nb*8 ----
        int i0 = e0 + (lane >> 2);
        int i1 = i0 + 8;
        int d0 = -1, d1 = -1;
        if (i0 < Etot) d0 = (i0 < Ereal) ? __ldg(dst + i0) : i0 - Ereal;
        if (i1 < Etot) d1 = (i1 < Ereal) ? __ldg(dst + i1) : i1 - Ereal;
        const int c0 = 2 * (lane & 3);
        #pragma unroll
        for (int nb = 0; nb < 16; nb++) {
            int c = c0 + nb * 8;
            if (d0 >= 0) redv2(agg + (size_t)d0 * 128 + c, acc[nb].x, acc[nb].y);
            if (d1 >= 0) redv2(agg + (size_t)d1 * 128 + c, acc[nb].z, acc[nb].w);
        }
    }
}

// ======================= small kernels =======================
__global__ void deg_kernel(const int* __restrict__ dst, int* __restrict__ deg, int E) {
    int i = blockIdx.x * blockDim.x + threadIdx.x;
    if (i < E) atomicAdd(&deg[dst[i]], 1);
}

// agg[n][c] = (deg[n]+1) * b2[c]   (folds per-message bias into target init)
__global__ void init_agg_kernel(float* __restrict__ agg, const int* __restrict__ deg,
                                const float* __restrict__ b2, int n) {
    int id = blockIdx.x * blockDim.x + threadIdx.x;
    if (id < n * 32) {
        int node = id >> 5, c = id & 31;
        float s = (float)(deg[node] + 1);
        float4 b = ((const float4*)b2)[c];
        ((float4*)(agg + (size_t)node * 128))[c] = make_float4(s * b.x, s * b.y, s * b.z, s * b.w);
    }
}

__global__ void pool_kernel(const float* __restrict__ agg, const int* __restrict__ batch,
                            float* __restrict__ pool, float* __restrict__ cnt, int n)
{
    int gw   = (blockIdx.x * blockDim.x + threadIdx.x) >> 5;
    int lane = threadIdx.x & 31;
    int nw   = (gridDim.x * blockDim.x) >> 5;
    for (int node = gw; node < n; node += nw) {
        int g = batch[node];
        float4 v = relu4(((const float4*)(agg + (size_t)node * 128))[lane]);
        float* p = pool + (size_t)g * 128 + lane * 4;
        atomicAdd(p + 0, v.x); atomicAdd(p + 1, v.y);
        atomicAdd(p + 2, v.z); atomicAdd(p + 3, v.w);
        if (lane == 0) atomicAdd(&cnt[g], 1.f);
    }
}

__global__ void final_kernel(const float* __restrict__ pool, const float* __restrict__ cnt,
                             const float* __restrict__ W, const float* __restrict__ b,
                             float* __restrict__ out)
{
    __shared__ float p[128];
    int g = blockIdx.x;
    float c = fmaxf(cnt[g], 1.f);
    for (int j = threadIdx.x; j < 128; j += blockDim.x)
        p[j] = pool[(size_t)g * 128 + j] / c;
    __syncthreads();
    int o = threadIdx.x;
    float s = b[o];
    #pragma unroll 4
    for (int j = 0; j < 128; j++) s += p[j] * W[j * 64 + o];
    out[(size_t)g * 64 + o] = s;
}

// ======================= launch =======================
extern "C" void kernel_launch(void* const* d_in, const int* in_sizes, int n_in,
                              void* d_out, int out_size)
{
    const float* x     = (const float*)d_in[0];
    const int*   ei    = (const int*)  d_in[1];
    const int*   batch = (const int*)  d_in[3];
    const int N = in_sizes[0] / 128;
    const int E = in_sizes[1] / 2;
    const int* src = ei;
    const int* dst = ei + E;

    const float* lin_w[3] = { (const float*)d_in[4],  (const float*)d_in[10], (const float*)d_in[16] };
    const float* lin_b[3] = { (const float*)d_in[5],  (const float*)d_in[11], (const float*)d_in[17] };
    const float* w1[3]    = { (const float*)d_in[6],  (const float*)d_in[12], (const float*)d_in[18] };
    const float* b1[3]    = { (const float*)d_in[7],  (const float*)d_in[13], (const float*)d_in[19] };
    const float* w2[3]    = { (const float*)d_in[8],  (const float*)d_in[14], (const float*)d_in[20] };
    const float* b2[3]    = { (const float*)d_in[9],  (const float*)d_in[15], (const float*)d_in[21] };
    const float* out_w    = (const float*)d_in[22];
    const float* out_b    = (const float*)d_in[23];
    float* out = (float*)d_out;

    float *h_, *A_, *B_, *agg_, *pool_, *cnt_;
    int* deg_;
    cudaGetSymbolAddress((void**)&h_,    g_h);
    cudaGetSymbolAddress((void**)&A_,    g_A);
    cudaGetSymbolAddress((void**)&B_,    g_B);
    cudaGetSymbolAddress((void**)&agg_,  g_agg);
    cudaGetSymbolAddress((void**)&pool_, g_pool);
    cudaGetSymbolAddress((void**)&cnt_,  g_cnt);
    cudaGetSymbolAddress((void**)&deg_,  g_deg);

    cudaFuncSetAttribute((const void*)gemm128_kernel<false>,
                         cudaFuncAttributeMaxDynamicSharedMemorySize, GEMM_SMEM);
    cudaFuncSetAttribute((const void*)gemm128_kernel<true>,
                         cudaFuncAttributeMaxDynamicSharedMemorySize, GEMM_SMEM);
    cudaFuncSetAttribute((const void*)edge_mma_kernel,
                         cudaFuncAttributeMaxDynamicSharedMemorySize, EDGE_SMEM);

    const int Etot   = E + N;
    const int ntasks = (Etot + 15) / 16;
    const int G = out_size / 64;

    cudaMemsetAsync(deg_, 0, (size_t)N * sizeof(int));
    deg_kernel<<<(E + 255) / 256, 256>>>(dst, deg_, E);

    for (int l = 0; l < 3; l++) {
        const float* X = (l == 0) ? x : agg_;
        if (l == 0)
            gemm128_kernel<false><<<NBLK, TPB_G, GEMM_SMEM>>>(X, lin_w[l], lin_b[l], h_, N);
        else
            gemm128_kernel<true ><<<NBLK, TPB_G, GEMM_SMEM>>>(X, lin_w[l], lin_b[l], h_, N);
        gemm128_kernel<false><<<NBLK, TPB_G, GEMM_SMEM>>>(h_, w1[l],             b1[l],  A_, N);
        gemm128_kernel<false><<<NBLK, TPB_G, GEMM_SMEM>>>(h_, w1[l] + 128 * 128, nullptr, B_, N);
        init_agg_kernel<<<(N * 32 + 255) / 256, 256>>>(agg_, deg_, b2[l], N);
        edge_mma_kernel<<<NBLK, TPB_E, EDGE_SMEM>>>(A_, B_, src, dst, w2[l], agg_, E, Etot, ntasks);
    }

    cudaMemsetAsync(pool_, 0, (size_t)G * 128 * sizeof(float));
    cudaMemsetAsync(cnt_,  0, (size_t)G * sizeof(float));
    pool_kernel<<<256, 256>>>(agg_, batch, pool_, cnt_, N);
    final_kernel<<<G, 64>>>(pool_, cnt_, out_w, out_b, out);
}

// round 7
// speedup vs baseline: 1.8689x; 1.1530x over previous
#include <cuda_runtime.h>
#include <cstdint>

#define NBLK   148

// ---- node gemm (f32x2, exact) ----
#define TPB_G   512
#define NWARP_G 16
#define RB      8
#define GEMM_SMEM (64*1024 + NWARP_G*RB*128*4)   // 128 KB

// ---- edge mma kernel ----
#define TPB_E   512
#define TILE16  (16*132)                          // 2112 floats per 16-edge sub-tile
#define TILE32  (2*TILE16)                        // 4224 floats per pair tile
#define WB_FLOATS (8*16*32*4)                     // 16384 floats = 64 KB (W2 frag layout)
#define EDGE_SMEM ((WB_FLOATS + 8*TILE32) * 4)    // 64KB + 132KB = 200704 B

// Scratch (device globals: allocation-free rule)
__device__ float g_h  [50000 * 128];
__device__ float g_A  [50000 * 128];
__device__ float g_B  [50000 * 128];
__device__ float g_agg[50000 * 128];
__device__ float g_pool[64 * 128];
__device__ float g_cnt [64];
__device__ int   g_deg [50000];

typedef unsigned long long u64;

__device__ __forceinline__ float4 relu4(float4 v) {
    v.x = fmaxf(v.x, 0.f); v.y = fmaxf(v.y, 0.f);
    v.z = fmaxf(v.z, 0.f); v.w = fmaxf(v.w, 0.f);
    return v;
}

// ======================= tf32 mma helpers =======================
__device__ __forceinline__ uint32_t f2tf32(float f) {
    uint32_t r; asm("cvt.rna.tf32.f32 %0, %1;" : "=r"(r) : "f"(f)); return r;
}
__device__ __forceinline__ void mma8(float4 &d, uint32_t a0, uint32_t a1,
                                     uint32_t a2, uint32_t a3,
                                     uint32_t b0, uint32_t b1) {
    asm volatile("mma.sync.aligned.m16n8k8.row.col.f32.tf32.tf32.f32 "
        "{%0,%1,%2,%3}, {%4,%5,%6,%7}, {%8,%9}, {%0,%1,%2,%3};"
        : "+f"(d.x), "+f"(d.y), "+f"(d.z), "+f"(d.w)
        : "r"(a0), "r"(a1), "r"(a2), "r"(a3), "r"(b0), "r"(b1));
}
// tf32-round a float4 fragment (straight order)
__device__ __forceinline__ void cvt4(float4 v, uint32_t h[4]) {
    h[0] = f2tf32(v.x); h[1] = f2tf32(v.y); h[2] = f2tf32(v.z); h[3] = f2tf32(v.w);
}
__device__ __forceinline__ void redv2(float* p, float a, float b) {
    asm volatile("red.global.add.v2.f32 [%0], {%1, %2};" :: "l"(p), "f"(a), "f"(b) : "memory");
}

// ======================= f32x2 node GEMM =======================
__device__ __forceinline__ void ffma2(u64 &acc, u64 a, u64 b) {
    asm("fma.rn.f32x2 %0, %1, %2, %0;" : "+l"(acc) : "l"(a), "l"(b));
}
__device__ __forceinline__ float pairsum(u64 p) {
    float lo, hi;
    asm("mov.b64 {%0, %1}, %2;" : "=f"(lo), "=f"(hi) : "l"(p));
    return lo + hi;
}
__device__ __forceinline__ u64 packf2(float lo, float hi) {
    u64 r;
    asm("mov.b64 %0, {%1, %2};" : "=l"(r) : "f"(lo), "f"(hi));
    return r;
}

__device__ __forceinline__ void stage_w_pairs(u64* Wp, const float* __restrict__ W) {
    for (int idx = threadIdx.x; idx < 64 * 128; idx += TPB_G) {
        int m = idx >> 7, n = idx & 127;
        Wp[idx] = packf2(W[(2 * m) * 128 + n], W[(2 * m + 1) * 128 + n]);
    }
}

__device__ __forceinline__ void mm_tile(u64 acc[RB][4], const float* tb, const u64* Wp, int lane) {
    #pragma unroll 2
    for (int mm = 0; mm < 32; mm++) {
        const u64* r0 = Wp + (2 * mm) * 128;
        const u64* r1 = Wp + (2 * mm + 1) * 128;
        ulonglong2 wa0 = ((const ulonglong2*)r0)[lane];
        ulonglong2 wb0 = ((const ulonglong2*)r0)[lane + 32];
        ulonglong2 wa1 = ((const ulonglong2*)r1)[lane];
        ulonglong2 wb1 = ((const ulonglong2*)r1)[lane + 32];
        #pragma unroll
        for (int e = 0; e < RB; e++) {
            ulonglong2 xp = ((const ulonglong2*)(tb + e * 128))[mm];
            ffma2(acc[e][0], xp.x, wa0.x);
            ffma2(acc[e][1], xp.x, wa0.y);
            ffma2(acc[e][2], xp.x, wb0.x);
            ffma2(acc[e][3], xp.x, wb0.y);
            ffma2(acc[e][0], xp.y, wa1.x);
            ffma2(acc[e][1], xp.y, wa1.y);
            ffma2(acc[e][2], xp.y, wb1.x);
            ffma2(acc[e][3], xp.y, wb1.y);
        }
    }
}

template <bool RELU_IN>
__global__ void __launch_bounds__(TPB_G, 1)
gemm128_kernel(const float* __restrict__ X, const float* __restrict__ W,
               const float* __restrict__ bias, float* __restrict__ Y, int nrows)
{
    extern __shared__ float sm[];
    u64*   Wp = (u64*)sm;
    float* xb = sm + 64 * 128 * 2;

    stage_w_pairs(Wp, W);
    __syncthreads();

    const int warp = threadIdx.x >> 5, lane = threadIdx.x & 31;
    float* tb = xb + warp * RB * 128;

    float2 b01 = make_float2(0.f, 0.f), b23 = make_float2(0.f, 0.f);
    if (bias) {
        b01 = ((const float2*)bias)[lane];
        b23 = ((const float2*)bias)[lane + 32];
    }

    const int gwarp  = blockIdx.x * NWARP_G + warp;
    const int nwarps = gridDim.x * NWARP_G;
    const int ntasks = (nrows + RB - 1) / RB;

    for (int task = gwarp; task < ntasks; task += nwarps) {
        const int row0 = task * RB;
        #pragma unroll
        for (int e = 0; e < RB; e++) {
            int r = row0 + e;
            float4 v = make_float4(0.f, 0.f, 0.f, 0.f);
            if (r < nrows) v = ((const float4*)(X + (size_t)r * 128))[lane];
            if (RELU_IN) v = relu4(v);
            ((float4*)(tb + e * 128))[lane] = v;
        }
        __syncwarp();

        u64 acc[RB][4];
        #pragma unroll
        for (int e = 0; e < RB; e++)
            acc[e][0] = acc[e][1] = acc[e][2] = acc[e][3] = 0ull;

        mm_tile(acc, tb, Wp, lane);

        #pragma unroll
        for (int e = 0; e < RB; e++) {
            int r = row0 + e;
            if (r < nrows) {
                float2 o01 = make_float2(pairsum(acc[e][0]) + b01.x, pairsum(acc[e][1]) + b01.y);
                float2 o23 = make_float2(pairsum(acc[e][2]) + b23.x, pairsum(acc[e][3]) + b23.y);
                ((float2*)(Y + (size_t)r * 128))[lane]      = o01;
                ((float2*)(Y + (size_t)r * 128))[lane + 32] = o23;
            }
        }
        __syncwarp();
    }
}

// ======================= edge kernel: tf32 mma.sync =======================
// Warp-pair owns 32 edges: each warp gathers 16 edges (half-tile), then both
// compute m32 x n64 x k128 (single tf32 pass) over the shared pair tile and
// scatter their n-half into agg[dst] via red.v2.
__global__ void __launch_bounds__(TPB_E, 1)
edge_mma_kernel(const float* __restrict__ A, const float* __restrict__ Bm,
                const int* __restrict__ src, const int* __restrict__ dst,
                const float* __restrict__ W2, float* __restrict__ agg,
                int Ereal, int Etot, int ntasks)
{
    extern __shared__ float sm[];
    float* Wb = sm;   // [8 kk2][16 nb][32 lane] uint4 tf32 B-fragments
    const int tid = threadIdx.x, wid = tid >> 5, lane = tid & 31;
    const int pairid = wid >> 1, half = wid & 1;
    float* ta    = sm + WB_FLOATS + pairid * TILE32;
    float* tmine = ta + half * TILE16;

    // Stage W2 (row-major [k][n]) into B-fragment layout, tf32-rounded, once.
    for (int i = tid; i < 4096; i += TPB_E) {
        int kk2 = i >> 9, rem = i & 511, nb = rem >> 5, ln = rem & 31;
        int n = nb * 8 + (ln >> 2), k = kk2 * 16 + (ln & 3);
        uint4 v;
        v.x = f2tf32(W2[(k     ) * 128 + n]);
        v.y = f2tf32(W2[(k +  4) * 128 + n]);
        v.z = f2tf32(W2[(k +  8) * 128 + n]);
        v.w = f2tf32(W2[(k + 12) * 128 + n]);
        ((uint4*)Wb)[i] = v;
    }
    __syncthreads();

    const int gpair = blockIdx.x * 8 + pairid;
    const int npair = gridDim.x * 8;
    const int sbase = (lane >> 1) * 132 + 2 * (lane & 1);
    const int barid = 1 + pairid;

    for (int task = gpair; task < ntasks; task += npair) {
        const int e0 = task * 32 + half * 16;

        // ---- gather 16 edges into this warp's half-tile ----
        #pragma unroll 4
        for (int e = 0; e < 16; e++) {
            int idx = e0 + e;
            float4 t = make_float4(0.f, 0.f, 0.f, 0.f);
            if (idx < Etot) {
                int s, d;
                if (idx < Ereal) { s = __ldg(src + idx); d = __ldg(dst + idx); }
                else             { s = d = idx - Ereal; }
                float4 a = ((const float4*)(A  + (size_t)d * 128))[lane];
                float4 b = ((const float4*)(Bm + (size_t)s * 128))[lane];
                t = relu4(make_float4(a.x + b.x, a.y + b.y, a.z + b.z, a.w + b.w));
            }
            float* p = tmine + sbase + (e & 7) * 16 + (e >> 3);
            p[0]  = t.x;
            p[4]  = t.y;
            p[8]  = t.z;
            p[12] = t.w;
        }
        asm volatile("bar.sync %0, 64;" :: "r"(barid) : "memory");

        // ---- mma: m32 x n64 x k128, single tf32 pass ----
        float4 acc[2][8];
        #pragma unroll
        for (int mf = 0; mf < 2; mf++)
            #pragma unroll
            for (int nb = 0; nb < 8; nb++) acc[mf][nb] = make_float4(0.f, 0.f, 0.f, 0.f);

        #pragma unroll
        for (int kk2 = 0; kk2 < 8; kk2++) {
            float4 ve0 = *(float4*)(ta +          (2 * kk2    ) * 132 + lane * 4);
            float4 vo0 = *(float4*)(ta +          (2 * kk2 + 1) * 132 + lane * 4);
            float4 ve1 = *(float4*)(ta + TILE16 + (2 * kk2    ) * 132 + lane * 4);
            float4 vo1 = *(float4*)(ta + TILE16 + (2 * kk2 + 1) * 132 + lane * 4);
            uint32_t he0[4], ho0[4], he1[4], ho1[4];
            cvt4(ve0, he0); cvt4(vo0, ho0); cvt4(ve1, he1); cvt4(vo1, ho1);

            const uint4* wrow = ((const uint4*)Wb) + kk2 * 512 + half * 256 + lane;
            #pragma unroll
            for (int nb = 0; nb < 8; nb++) {
                uint4 B = wrow[nb * 32];
                mma8(acc[0][nb], he0[0], he0[1], he0[2], he0[3], B.x, B.y);
                mma8(acc[0][nb], ho0[0], ho0[1], ho0[2], ho0[3], B.z, B.w);
                mma8(acc[1][nb], he1[0], he1[1], he1[2], he1[3], B.x, B.y);
                mma8(acc[1][nb], ho1[0], ho1[1], ho1[2], ho1[3], B.z, B.w);
            }
        }
        asm volatile("bar.sync %0, 64;" :: "r"(barid) : "memory");

        // ---- scatter: this warp's n-half (64 cols) for all 32 edges ----
        const int c0 = half * 64 + 2 * (lane & 3);
        #pragma unroll
        for (int mf = 0; mf < 2; mf++) {
            int i0 = task * 32 + mf * 16 + (lane >> 2);
            int i1 = i0 + 8;
            int d0 = -1, d1 = -1;
            if (i0 < Etot) d0 = (i0 < Ereal) ? __ldg(dst + i0) : i0 - Ereal;
            if (i1 < Etot) d1 = (i1 < Ereal) ? __ldg(dst + i1) : i1 - Ereal;
            #pragma unroll
            for (int nb = 0; nb < 8; nb++) {
                int c = c0 + nb * 8;
                if (d0 >= 0) redv2(agg + (size_t)d0 * 128 + c, acc[mf][nb].x, acc[mf][nb].y);
                if (d1 >= 0) redv2(agg + (size_t)d1 * 128 + c, acc[mf][nb].z, acc[mf][nb].w);
            }
        }
    }
}

// ======================= small kernels =======================
__global__ void deg_kernel(const int* __restrict__ dst, int* __restrict__ deg, int E) {
    int i = blockIdx.x * blockDim.x + threadIdx.x;
    if (i < E) atomicAdd(&deg[dst[i]], 1);
}

// agg[n][c] = (deg[n]+1) * b2[c]   (folds per-message bias into target init)
__global__ void init_agg_kernel(float* __restrict__ agg, const int* __restrict__ deg,
                                const float* __restrict__ b2, int n) {
    int id = blockIdx.x * blockDim.x + threadIdx.x;
    if (id < n * 32) {
        int node = id >> 5, c = id & 31;
        float s = (float)(deg[node] + 1);
        float4 b = ((const float4*)b2)[c];
        ((float4*)(agg + (size_t)node * 128))[c] = make_float4(s * b.x, s * b.y, s * b.z, s * b.w);
    }
}

__global__ void pool_kernel(const float* __restrict__ agg, const int* __restrict__ batch,
                            float* __restrict__ pool, float* __restrict__ cnt, int n)
{
    int gw   = (blockIdx.x * blockDim.x + threadIdx.x) >> 5;
    int lane = threadIdx.x & 31;
    int nw   = (gridDim.x * blockDim.x) >> 5;
    for (int node = gw; node < n; node += nw) {
        int g = batch[node];
        float4 v = relu4(((const float4*)(agg + (size_t)node * 128))[lane]);
        float* p = pool + (size_t)g * 128 + lane * 4;
        atomicAdd(p + 0, v.x); atomicAdd(p + 1, v.y);
        atomicAdd(p + 2, v.z); atomicAdd(p + 3, v.w);
        if (lane == 0) atomicAdd(&cnt[g], 1.f);
    }
}

__global__ void final_kernel(const float* __restrict__ pool, const float* __restrict__ cnt,
                             const float* __restrict__ W, const float* __restrict__ b,
                             float* __restrict__ out)
{
    __shared__ float p[128];
    int g = blockIdx.x;
    float c = fmaxf(cnt[g], 1.f);
    for (int j = threadIdx.x; j < 128; j += blockDim.x)
        p[j] = pool[(size_t)g * 128 + j] / c;
    __syncthreads();
    int o = threadIdx.x;
    float s = b[o];
    #pragma unroll 4
    for (int j = 0; j < 128; j++) s += p[j] * W[j * 64 + o];
    out[(size_t)g * 64 + o] = s;
}

// ======================= launch =======================
extern "C" void kernel_launch(void* const* d_in, const int* in_sizes, int n_in,
                              void* d_out, int out_size)
{
    const float* x     = (const float*)d_in[0];
    const int*   ei    = (const int*)  d_in[1];
    const int*   batch = (const int*)  d_in[3];
    const int N = in_sizes[0] / 128;
    const int E = in_sizes[1] / 2;
    const int* src = ei;
    const int* dst = ei + E;

    const float* lin_w[3] = { (const float*)d_in[4],  (const float*)d_in[10], (const float*)d_in[16] };
    const float* lin_b[3] = { (const float*)d_in[5],  (const float*)d_in[11], (const float*)d_in[17] };
    const float* w1[3]    = { (const float*)d_in[6],  (const float*)d_in[12], (const float*)d_in[18] };
    const float* b1[3]    = { (const float*)d_in[7],  (const float*)d_in[13], (const float*)d_in[19] };
    const float* w2[3]    = { (const float*)d_in[8],  (const float*)d_in[14], (const float*)d_in[20] };
    const float* b2[3]    = { (const float*)d_in[9],  (const float*)d_in[15], (const float*)d_in[21] };
    const float* out_w    = (const float*)d_in[22];
    const float* out_b    = (const float*)d_in[23];
    float* out = (float*)d_out;

    float *h_, *A_, *B_, *agg_, *pool_, *cnt_;
    int* deg_;
    cudaGetSymbolAddress((void**)&h_,    g_h);
    cudaGetSymbolAddress((void**)&A_,    g_A);
    cudaGetSymbolAddress((void**)&B_,    g_B);
    cudaGetSymbolAddress((void**)&agg_,  g_agg);
    cudaGetSymbolAddress((void**)&pool_, g_pool);
    cudaGetSymbolAddress((void**)&cnt_,  g_cnt);
    cudaGetSymbolAddress((void**)&deg_,  g_deg);

    cudaFuncSetAttribute((const void*)gemm128_kernel<false>,
                         cudaFuncAttributeMaxDynamicSharedMemorySize, GEMM_SMEM);
    cudaFuncSetAttribute((const void*)gemm128_kernel<true>,
                         cudaFuncAttributeMaxDynamicSharedMemorySize, GEMM_SMEM);
    cudaFuncSetAttribute((const void*)edge_mma_kernel,
                         cudaFuncAttributeMaxDynamicSharedMemorySize, EDGE_SMEM);

    const int Etot   = E + N;
    const int ntasks = (Etot + 31) / 32;
    const int G = out_size / 64;

    cudaMemsetAsync(deg_, 0, (size_t)N * sizeof(int));
    deg_kernel<<<(E + 255) / 256, 256>>>(dst, deg_, E);

    for (int l = 0; l < 3; l++) {
        const float* X = (l == 0) ? x : agg_;
        if (l == 0)
            gemm128_kernel<false><<<NBLK, TPB_G, GEMM_SMEM>>>(X, lin_w[l], lin_b[l], h_, N);
        else
            gemm128_kernel<true ><<<NBLK, TPB_G, GEMM_SMEM>>>(X, lin_w[l], lin_b[l], h_, N);
        gemm128_kernel<false><<<NBLK, TPB_G, GEMM_SMEM>>>(h_, w1[l],             b1[l],  A_, N);
        gemm128_kernel<false><<<NBLK, TPB_G, GEMM_SMEM>>>(h_, w1[l] + 128 * 128, nullptr, B_, N);
        init_agg_kernel<<<(N * 32 + 255) / 256, 256>>>(agg_, deg_, b2[l], N);
        edge_mma_kernel<<<NBLK, TPB_E, EDGE_SMEM>>>(A_, B_, src, dst, w2[l], agg_, E, Etot, ntasks);
    }

    cudaMemsetAsync(pool_, 0, (size_t)G * 128 * sizeof(float));
    cudaMemsetAsync(cnt_,  0, (size_t)G * sizeof(float));
    pool_kernel<<<256, 256>>>(agg_, batch, pool_, cnt_, N);
    final_kernel<<<G, 64>>>(pool_, cnt_, out_w, out_b, out);
}

// round 8
// speedup vs baseline: 2.0455x; 1.0945x over previous
#include <cuda_runtime.h>
#include <cstdint>

#define NBLK   148

// ---- shared mma kernel config ----
#define TPB_E   512
#define TILE16  (16*132)                          // 2112 floats per 16-row sub-tile
#define TILE32  (2*TILE16)
#define WB_FLOATS (8*16*32*4)                     // 16384 floats = 64 KB (W frag layout)
#define MMA_SMEM ((WB_FLOATS + 8*TILE32) * 4)     // 64KB + 132KB = 200704 B

// Scratch (device globals: allocation-free rule)
__device__ float g_h  [50000 * 128];
__device__ float g_A  [50000 * 128];
__device__ float g_B  [50000 * 128];
__device__ float g_agg[50000 * 128];
__device__ float g_pool[64 * 128];
__device__ float g_cnt [64];
__device__ int   g_deg [50000];

__device__ __forceinline__ float4 relu4(float4 v) {
    v.x = fmaxf(v.x, 0.f); v.y = fmaxf(v.y, 0.f);
    v.z = fmaxf(v.z, 0.f); v.w = fmaxf(v.w, 0.f);
    return v;
}

// ======================= tf32 mma helpers =======================
__device__ __forceinline__ uint32_t f2tf32(float f) {
    uint32_t r; asm("cvt.rna.tf32.f32 %0, %1;" : "=r"(r) : "f"(f)); return r;
}
__device__ __forceinline__ void mma8(float4 &d, const uint32_t a[4],
                                     uint32_t b0, uint32_t b1) {
    asm volatile("mma.sync.aligned.m16n8k8.row.col.f32.tf32.tf32.f32 "
        "{%0,%1,%2,%3}, {%4,%5,%6,%7}, {%8,%9}, {%0,%1,%2,%3};"
        : "+f"(d.x), "+f"(d.y), "+f"(d.z), "+f"(d.w)
        : "r"(a[0]), "r"(a[1]), "r"(a[2]), "r"(a[3]), "r"(b0), "r"(b1));
}
// tf32-round fragment (straight order)
__device__ __forceinline__ void cvt4(float4 v, uint32_t h[4]) {
    h[0] = f2tf32(v.x); h[1] = f2tf32(v.y); h[2] = f2tf32(v.z); h[3] = f2tf32(v.w);
}
// hi/lo split (straight order)
__device__ __forceinline__ void split4hl(float4 v, uint32_t h[4], uint32_t l[4]) {
    h[0] = f2tf32(v.x); l[0] = f2tf32(v.x - __uint_as_float(h[0]));
    h[1] = f2tf32(v.y); l[1] = f2tf32(v.y - __uint_as_float(h[1]));
    h[2] = f2tf32(v.z); l[2] = f2tf32(v.z - __uint_as_float(h[2]));
    h[3] = f2tf32(v.w); l[3] = f2tf32(v.w - __uint_as_float(h[3]));
}
__device__ __forceinline__ void redv2(float* p, float a, float b) {
    asm volatile("red.global.add.v2.f32 [%0], {%1, %2};" :: "l"(p), "f"(a), "f"(b) : "memory");
}

// Stage W (row-major [k][n], 128x128) into B-fragment layout, tf32-rounded.
__device__ __forceinline__ void stage_w_frag(float* Wb, const float* __restrict__ W) {
    for (int i = threadIdx.x; i < 4096; i += TPB_E) {
        int kk2 = i >> 9, rem = i & 511, nb = rem >> 5, ln = rem & 31;
        int n = nb * 8 + (ln >> 2), k = kk2 * 16 + (ln & 3);
        uint4 v;
        v.x = f2tf32(W[(k     ) * 128 + n]);
        v.y = f2tf32(W[(k +  4) * 128 + n]);
        v.z = f2tf32(W[(k +  8) * 128 + n]);
        v.w = f2tf32(W[(k + 12) * 128 + n]);
        ((uint4*)Wb)[i] = v;
    }
}

// ======================= node GEMM: tf32 mma, hi/lo compensated =======================
// Y[r] = (RELU_IN ? relu(X[r]) : X[r]) @ W + bias.  Warp owns 16 sequential rows,
// m16 x n128 x k128, activations split hi+lo (2 passes) -> only W truncation remains.
template <bool RELU_IN>
__global__ void __launch_bounds__(TPB_E, 1)
node_mma_kernel(const float* __restrict__ X, const float* __restrict__ W,
                const float* __restrict__ bias, float* __restrict__ Y, int nrows)
{
    extern __shared__ float sm[];
    float* Wb = sm;
    const int tid = threadIdx.x, wid = tid >> 5, lane = tid & 31;
    float* ta = sm + WB_FLOATS + wid * TILE16;

    stage_w_frag(Wb, W);
    __syncthreads();

    const int gwarp  = blockIdx.x * 16 + wid;
    const int nwarps = gridDim.x * 16;
    const int ntasks = (nrows + 15) / 16;
    const int sbase  = (lane >> 1) * 132 + 2 * (lane & 1);

    for (int task = gwarp; task < ntasks; task += nwarps) {
        const int r0 = task * 16;

        #pragma unroll 4
        for (int e = 0; e < 16; e++) {
            int r = r0 + e;
            float4 t = make_float4(0.f, 0.f, 0.f, 0.f);
            if (r < nrows) {
                t = ((const float4*)(X + (size_t)r * 128))[lane];
                if (RELU_IN) t = relu4(t);
            }
            float* p = ta + sbase + (e & 7) * 16 + (e >> 3);
            p[0]  = t.x;
            p[4]  = t.y;
            p[8]  = t.z;
            p[12] = t.w;
        }
        __syncwarp();

        float4 acc[16];
        #pragma unroll
        for (int nb = 0; nb < 16; nb++) acc[nb] = make_float4(0.f, 0.f, 0.f, 0.f);

        #pragma unroll
        for (int kk2 = 0; kk2 < 8; kk2++) {
            float4 ve = *(float4*)(ta + (2 * kk2    ) * 132 + lane * 4);
            float4 vo = *(float4*)(ta + (2 * kk2 + 1) * 132 + lane * 4);
            uint32_t he[4], le[4], ho[4], lo[4];
            split4hl(ve, he, le);
            split4hl(vo, ho, lo);

            const uint4* wrow = ((const uint4*)Wb) + kk2 * 512 + lane;
            #pragma unroll
            for (int nb = 0; nb < 16; nb++) {
                uint4 B = wrow[nb * 32];
                mma8(acc[nb], he, B.x, B.y);
                mma8(acc[nb], le, B.x, B.y);
                mma8(acc[nb], ho, B.z, B.w);
                mma8(acc[nb], lo, B.z, B.w);
            }
        }
        __syncwarp();

        // store D fragments (+bias)
        int i0 = r0 + (lane >> 2);
        int i1 = i0 + 8;
        #pragma unroll
        for (int nb = 0; nb < 16; nb++) {
            int c = 2 * (lane & 3) + nb * 8;
            float b0 = 0.f, b1 = 0.f;
            if (bias) { b0 = __ldg(bias + c); b1 = __ldg(bias + c + 1); }
            if (i0 < nrows)
                *(float2*)(Y + (size_t)i0 * 128 + c) = make_float2(acc[nb].x + b0, acc[nb].y + b1);
            if (i1 < nrows)
                *(float2*)(Y + (size_t)i1 * 128 + c) = make_float2(acc[nb].z + b0, acc[nb].w + b1);
        }
    }
}

// ======================= edge kernel: tf32 mma.sync (unchanged from R7) =======================
__global__ void __launch_bounds__(TPB_E, 1)
edge_mma_kernel(const float* __restrict__ A, const float* __restrict__ Bm,
                const int* __restrict__ src, const int* __restrict__ dst,
                const float* __restrict__ W2, float* __restrict__ agg,
                int Ereal, int Etot, int ntasks)
{
    extern __shared__ float sm[];
    float* Wb = sm;
    const int tid = threadIdx.x, wid = tid >> 5, lane = tid & 31;
    const int pairid = wid >> 1, half = wid & 1;
    float* ta    = sm + WB_FLOATS + pairid * TILE32;
    float* tmine = ta + half * TILE16;

    stage_w_frag(Wb, W2);
    __syncthreads();

    const int gpair = blockIdx.x * 8 + pairid;
    const int npair = gridDim.x * 8;
    const int sbase = (lane >> 1) * 132 + 2 * (lane & 1);
    const int barid = 1 + pairid;

    for (int task = gpair; task < ntasks; task += npair) {
        const int e0 = task * 32 + half * 16;

        #pragma unroll 4
        for (int e = 0; e < 16; e++) {
            int idx = e0 + e;
            float4 t = make_float4(0.f, 0.f, 0.f, 0.f);
            if (idx < Etot) {
                int s, d;
                if (idx < Ereal) { s = __ldg(src + idx); d = __ldg(dst + idx); }
                else             { s = d = idx - Ereal; }
                float4 a = ((const float4*)(A  + (size_t)d * 128))[lane];
                float4 b = ((const float4*)(Bm + (size_t)s * 128))[lane];
                t = relu4(make_float4(a.x + b.x, a.y + b.y, a.z + b.z, a.w + b.w));
            }
            float* p = tmine + sbase + (e & 7) * 16 + (e >> 3);
            p[0]  = t.x;
            p[4]  = t.y;
            p[8]  = t.z;
            p[12] = t.w;
        }
        asm volatile("bar.sync %0, 64;" :: "r"(barid) : "memory");

        float4 acc[2][8];
        #pragma unroll
        for (int mf = 0; mf < 2; mf++)
            #pragma unroll
            for (int nb = 0; nb < 8; nb++) acc[mf][nb] = make_float4(0.f, 0.f, 0.f, 0.f);

        #pragma unroll
        for (int kk2 = 0; kk2 < 8; kk2++) {
            float4 ve0 = *(float4*)(ta +          (2 * kk2    ) * 132 + lane * 4);
            float4 vo0 = *(float4*)(ta +          (2 * kk2 + 1) * 132 + lane * 4);
            float4 ve1 = *(float4*)(ta + TILE16 + (2 * kk2    ) * 132 + lane * 4);
            float4 vo1 = *(float4*)(ta + TILE16 + (2 * kk2 + 1) * 132 + lane * 4);
            uint32_t he0[4], ho0[4], he1[4], ho1[4];
            cvt4(ve0, he0); cvt4(vo0, ho0); cvt4(ve1, he1); cvt4(vo1, ho1);

            const uint4* wrow = ((const uint4*)Wb) + kk2 * 512 + half * 256 + lane;
            #pragma unroll
            for (int nb = 0; nb < 8; nb++) {
                uint4 B = wrow[nb * 32];
                mma8(acc[0][nb], he0, B.x, B.y);
                mma8(acc[0][nb], ho0, B.z, B.w);
                mma8(acc[1][nb], he1, B.x, B.y);
                mma8(acc[1][nb], ho1, B.z, B.w);
            }
        }
        asm volatile("bar.sync %0, 64;" :: "r"(barid) : "memory");

        const int c0 = half * 64 + 2 * (lane & 3);
        #pragma unroll
        for (int mf = 0; mf < 2; mf++) {
            int i0 = task * 32 + mf * 16 + (lane >> 2);
            int i1 = i0 + 8;
            int d0 = -1, d1 = -1;
            if (i0 < Etot) d0 = (i0 < Ereal) ? __ldg(dst + i0) : i0 - Ereal;
            if (i1 < Etot) d1 = (i1 < Ereal) ? __ldg(dst + i1) : i1 - Ereal;
            #pragma unroll
            for (int nb = 0; nb < 8; nb++) {
                int c = c0 + nb * 8;
                if (d0 >= 0) redv2(agg + (size_t)d0 * 128 + c, acc[mf][nb].x, acc[mf][nb].y);
                if (d1 >= 0) redv2(agg + (size_t)d1 * 128 + c, acc[mf][nb].z, acc[mf][nb].w);
            }
        }
    }
}

// ======================= small kernels =======================
__global__ void deg_kernel(const int* __restrict__ dst, int* __restrict__ deg, int E) {
    int i = blockIdx.x * blockDim.x + threadIdx.x;
    if (i < E) atomicAdd(&deg[dst[i]], 1);
}

__global__ void init_agg_kernel(float* __restrict__ agg, const int* __restrict__ deg,
                                const float* __restrict__ b2, int n) {
    int id = blockIdx.x * blockDim.x + threadIdx.x;
    if (id < n * 32) {
        int node = id >> 5, c = id & 31;
        float s = (float)(deg[node] + 1);
        float4 b = ((const float4*)b2)[c];
        ((float4*)(agg + (size_t)node * 128))[c] = make_float4(s * b.x, s * b.y, s * b.z, s * b.w);
    }
}

__global__ void pool_kernel(const float* __restrict__ agg, const int* __restrict__ batch,
                            float* __restrict__ pool, float* __restrict__ cnt, int n)
{
    int gw   = (blockIdx.x * blockDim.x + threadIdx.x) >> 5;
    int lane = threadIdx.x & 31;
    int nw   = (gridDim.x * blockDim.x) >> 5;
    for (int node = gw; node < n; node += nw) {
        int g = batch[node];
        float4 v = relu4(((const float4*)(agg + (size_t)node * 128))[lane]);
        float* p = pool + (size_t)g * 128 + lane * 4;
        atomicAdd(p + 0, v.x); atomicAdd(p + 1, v.y);
        atomicAdd(p + 2, v.z); atomicAdd(p + 3, v.w);
        if (lane == 0) atomicAdd(&cnt[g], 1.f);
    }
}

__global__ void final_kernel(const float* __restrict__ pool, const float* __restrict__ cnt,
                             const float* __restrict__ W, const float* __restrict__ b,
                             float* __restrict__ out)
{
    __shared__ float p[128];
    int g = blockIdx.x;
    float c = fmaxf(cnt[g], 1.f);
    for (int j = threadIdx.x; j < 128; j += blockDim.x)
        p[j] = pool[(size_t)g * 128 + j] / c;
    __syncthreads();
    int o = threadIdx.x;
    float s = b[o];
    #pragma unroll 4
    for (int j = 0; j < 128; j++) s += p[j] * W[j * 64 + o];
    out[(size_t)g * 64 + o] = s;
}

// ======================= launch =======================
extern "C" void kernel_launch(void* const* d_in, const int* in_sizes, int n_in,
                              void* d_out, int out_size)
{
    const float* x     = (const float*)d_in[0];
    const int*   ei    = (const int*)  d_in[1];
    const int*   batch = (const int*)  d_in[3];
    const int N = in_sizes[0] / 128;
    const int E = in_sizes[1] / 2;
    const int* src = ei;
    const int* dst = ei + E;

    const float* lin_w[3] = { (const float*)d_in[4],  (const float*)d_in[10], (const float*)d_in[16] };
    const float* lin_b[3] = { (const float*)d_in[5],  (const float*)d_in[11], (const float*)d_in[17] };
    const float* w1[3]    = { (const float*)d_in[6],  (const float*)d_in[12], (const float*)d_in[18] };
    const float* b1[3]    = { (const float*)d_in[7],  (const float*)d_in[13], (const float*)d_in[19] };
    const float* w2[3]    = { (const float*)d_in[8],  (const float*)d_in[14], (const float*)d_in[20] };
    const float* b2[3]    = { (const float*)d_in[9],  (const float*)d_in[15], (const float*)d_in[21] };
    const float* out_w    = (const float*)d_in[22];
    const float* out_b    = (const float*)d_in[23];
    float* out = (float*)d_out;

    float *h_, *A_, *B_, *agg_, *pool_, *cnt_;
    int* deg_;
    cudaGetSymbolAddress((void**)&h_,    g_h);
    cudaGetSymbolAddress((void**)&A_,    g_A);
    cudaGetSymbolAddress((void**)&B_,    g_B);
    cudaGetSymbolAddress((void**)&agg_,  g_agg);
    cudaGetSymbolAddress((void**)&pool_, g_pool);
    cudaGetSymbolAddress((void**)&cnt_,  g_cnt);
    cudaGetSymbolAddress((void**)&deg_,  g_deg);

    cudaFuncSetAttribute((const void*)node_mma_kernel<false>,
                         cudaFuncAttributeMaxDynamicSharedMemorySize, MMA_SMEM);
    cudaFuncSetAttribute((const void*)node_mma_kernel<true>,
                         cudaFuncAttributeMaxDynamicSharedMemorySize, MMA_SMEM);
    cudaFuncSetAttribute((const void*)edge_mma_kernel,
                         cudaFuncAttributeMaxDynamicSharedMemorySize, MMA_SMEM);

    const int Etot   = E + N;
    const int ntasks = (Etot + 31) / 32;
    const int G = out_size / 64;

    cudaMemsetAsync(deg_, 0, (size_t)N * sizeof(int));
    deg_kernel<<<(E + 255) / 256, 256>>>(dst, deg_, E);

    for (int l = 0; l < 3; l++) {
        const float* X = (l == 0) ? x : agg_;
        if (l == 0)
            node_mma_kernel<false><<<NBLK, TPB_E, MMA_SMEM>>>(X, lin_w[l], lin_b[l], h_, N);
        else
            node_mma_kernel<true ><<<NBLK, TPB_E, MMA_SMEM>>>(X, lin_w[l], lin_b[l], h_, N);
        node_mma_kernel<false><<<NBLK, TPB_E, MMA_SMEM>>>(h_, w1[l],             b1[l],  A_, N);
        node_mma_kernel<false><<<NBLK, TPB_E, MMA_SMEM>>>(h_, w1[l] + 128 * 128, nullptr, B_, N);
        init_agg_kernel<<<(N * 32 + 255) / 256, 256>>>(agg_, deg_, b2[l], N);
        edge_mma_kernel<<<NBLK, TPB_E, MMA_SMEM>>>(A_, B_, src, dst, w2[l], agg_, E, Etot, ntasks);
    }

    cudaMemsetAsync(pool_, 0, (size_t)G * 128 * sizeof(float));
    cudaMemsetAsync(cnt_,  0, (size_t)G * sizeof(float));
    pool_kernel<<<256, 256>>>(agg_, batch, pool_, cnt_, N);
    final_kernel<<<G, 64>>>(pool_, cnt_, out_w, out_b, out);
}

// round 9
// speedup vs baseline: 4.1091x; 2.0088x over previous
#include <cuda_runtime.h>
#include <cstdint>

#define NBLK   148

// ---- mma kernel config ----
#define TPB_E   512
#define TILE16  (16*132)                          // 2112 floats per 16-row sub-tile
#define WB_FLOATS (8*16*32*4)                     // 16384 floats = 64 KB (W frag layout)
#define MMA_SMEM ((WB_FLOATS + 16*TILE16) * 4)    // 64KB + 132KB = 200704 B

// Scratch (device globals: allocation-free rule)
__device__ float g_h   [50000 * 128];
__device__ float g_A   [50000 * 128];
__device__ float g_B   [50000 * 128];
__device__ float g_T   [50000 * 128];
__device__ float g_agg [50000 * 128];
__device__ float g_pool[64 * 128];
__device__ float g_cnt [64];
__device__ int   g_deg [50000];
__device__ int   g_start[50001];
__device__ int   g_cursor[50000];
__device__ int   g_ssrc[800000];

__device__ __forceinline__ float4 relu4(float4 v) {
    v.x = fmaxf(v.x, 0.f); v.y = fmaxf(v.y, 0.f);
    v.z = fmaxf(v.z, 0.f); v.w = fmaxf(v.w, 0.f);
    return v;
}

// ======================= tf32 mma helpers =======================
__device__ __forceinline__ uint32_t f2tf32(float f) {
    uint32_t r; asm("cvt.rna.tf32.f32 %0, %1;" : "=r"(r) : "f"(f)); return r;
}
__device__ __forceinline__ void mma8(float4 &d, const uint32_t a[4],
                                     uint32_t b0, uint32_t b1) {
    asm volatile("mma.sync.aligned.m16n8k8.row.col.f32.tf32.tf32.f32 "
        "{%0,%1,%2,%3}, {%4,%5,%6,%7}, {%8,%9}, {%0,%1,%2,%3};"
        : "+f"(d.x), "+f"(d.y), "+f"(d.z), "+f"(d.w)
        : "r"(a[0]), "r"(a[1]), "r"(a[2]), "r"(a[3]), "r"(b0), "r"(b1));
}
// hi/lo split (straight order)
__device__ __forceinline__ void split4hl(float4 v, uint32_t h[4], uint32_t l[4]) {
    h[0] = f2tf32(v.x); l[0] = f2tf32(v.x - __uint_as_float(h[0]));
    h[1] = f2tf32(v.y); l[1] = f2tf32(v.y - __uint_as_float(h[1]));
    h[2] = f2tf32(v.z); l[2] = f2tf32(v.z - __uint_as_float(h[2]));
    h[3] = f2tf32(v.w); l[3] = f2tf32(v.w - __uint_as_float(h[3]));
}

// Stage W (row-major [k][n], 128x128) into B-fragment layout, tf32-rounded.
__device__ __forceinline__ void stage_w_frag(float* Wb, const float* __restrict__ W) {
    for (int i = threadIdx.x; i < 4096; i += TPB_E) {
        int kk2 = i >> 9, rem = i & 511, nb = rem >> 5, ln = rem & 31;
        int n = nb * 8 + (ln >> 2), k = kk2 * 16 + (ln & 3);
        uint4 v;
        v.x = f2tf32(W[(k     ) * 128 + n]);
        v.y = f2tf32(W[(k +  4) * 128 + n]);
        v.z = f2tf32(W[(k +  8) * 128 + n]);
        v.w = f2tf32(W[(k + 12) * 128 + n]);
        ((uint4*)Wb)[i] = v;
    }
}

// ======================= node GEMM: tf32 mma, hi/lo compensated =======================
// Y[r] = (RELU_IN ? relu(X[r]) : X[r]) @ W + bias_scale * bias
// DEGBIAS: bias scaled per-row by (deg[r]+1).
template <bool RELU_IN, bool DEGBIAS>
__global__ void __launch_bounds__(TPB_E, 1)
node_mma_kernel(const float* __restrict__ X, const float* __restrict__ W,
                const float* __restrict__ bias, const int* __restrict__ degp,
                float* __restrict__ Y, int nrows)
{
    extern __shared__ float sm[];
    float* Wb = sm;
    const int tid = threadIdx.x, wid = tid >> 5, lane = tid & 31;
    float* ta = sm + WB_FLOATS + wid * TILE16;

    stage_w_frag(Wb, W);
    __syncthreads();

    const int gwarp  = blockIdx.x * 16 + wid;
    const int nwarps = gridDim.x * 16;
    const int ntasks = (nrows + 15) / 16;
    const int sbase  = (lane >> 1) * 132 + 2 * (lane & 1);

    for (int task = gwarp; task < ntasks; task += nwarps) {
        const int r0 = task * 16;

        #pragma unroll 4
        for (int e = 0; e < 16; e++) {
            int r = r0 + e;
            float4 t = make_float4(0.f, 0.f, 0.f, 0.f);
            if (r < nrows) {
                t = ((const float4*)(X + (size_t)r * 128))[lane];
                if (RELU_IN) t = relu4(t);
            }
            float* p = ta + sbase + (e & 7) * 16 + (e >> 3);
            p[0]  = t.x;
            p[4]  = t.y;
            p[8]  = t.z;
            p[12] = t.w;
        }
        __syncwarp();

        float4 acc[16];
        #pragma unroll
        for (int nb = 0; nb < 16; nb++) acc[nb] = make_float4(0.f, 0.f, 0.f, 0.f);

        #pragma unroll
        for (int kk2 = 0; kk2 < 8; kk2++) {
            float4 ve = *(float4*)(ta + (2 * kk2    ) * 132 + lane * 4);
            float4 vo = *(float4*)(ta + (2 * kk2 + 1) * 132 + lane * 4);
            uint32_t he[4], le[4], ho[4], lo[4];
            split4hl(ve, he, le);
            split4hl(vo, ho, lo);

            const uint4* wrow = ((const uint4*)Wb) + kk2 * 512 + lane;
            #pragma unroll
            for (int nb = 0; nb < 16; nb++) {
                uint4 B = wrow[nb * 32];
                mma8(acc[nb], he, B.x, B.y);
                mma8(acc[nb], le, B.x, B.y);
                mma8(acc[nb], ho, B.z, B.w);
                mma8(acc[nb], lo, B.z, B.w);
            }
        }
        __syncwarp();

        // store D fragments (+bias)
        int i0 = r0 + (lane >> 2);
        int i1 = i0 + 8;
        float s0 = 1.f, s1 = 1.f;
        if (DEGBIAS) {
            if (i0 < nrows) s0 = (float)(__ldg(degp + i0) + 1);
            if (i1 < nrows) s1 = (float)(__ldg(degp + i1) + 1);
        }
        #pragma unroll
        for (int nb = 0; nb < 16; nb++) {
            int c = 2 * (lane & 3) + nb * 8;
            float b0 = 0.f, b1 = 0.f;
            if (bias) { b0 = __ldg(bias + c); b1 = __ldg(bias + c + 1); }
            if (i0 < nrows)
                *(float2*)(Y + (size_t)i0 * 128 + c) = make_float2(acc[nb].x + s0 * b0, acc[nb].y + s0 * b1);
            if (i1 < nrows)
                *(float2*)(Y + (size_t)i1 * 128 + c) = make_float2(acc[nb].z + s1 * b0, acc[nb].w + s1 * b1);
        }
    }
}

// ======================= CSR build =======================
__global__ void deg_kernel(const int* __restrict__ dst, int* __restrict__ deg, int E) {
    int i = blockIdx.x * blockDim.x + threadIdx.x;
    if (i < E) atomicAdd(&deg[dst[i]], 1);
}

// Single-block exclusive prefix sum over deg[0..n), writes start[0..n] and cursor.
__global__ void scan_kernel(const int* __restrict__ deg, int* __restrict__ start,
                            int* __restrict__ cursor, int n)
{
    __shared__ int carry;
    __shared__ int wsum[32];
    const int tidx = threadIdx.x, lane = tidx & 31, wid = tidx >> 5;
    if (tidx == 0) carry = 0;
    __syncthreads();

    for (int base = 0; base < n; base += 1024) {
        int i = base + tidx;
        int v = (i < n) ? deg[i] : 0;
        // inclusive warp scan
        int x = v;
        #pragma unroll
        for (int o = 1; o < 32; o <<= 1) {
            int y = __shfl_up_sync(0xffffffffu, x, o);
            if (lane >= o) x += y;
        }
        if (lane == 31) wsum[wid] = x;
        __syncthreads();
        if (wid == 0) {
            int w = wsum[lane];
            #pragma unroll
            for (int o = 1; o < 32; o <<= 1) {
                int y = __shfl_up_sync(0xffffffffu, w, o);
                if (lane >= o) w += y;
            }
            wsum[lane] = w;
        }
        __syncthreads();
        int excl = x - v + (wid > 0 ? wsum[wid - 1] : 0) + carry;
        if (i < n) { start[i] = excl; cursor[i] = excl; }
        int blocktot = wsum[31];
        __syncthreads();
        if (tidx == 0) carry += blocktot;
        __syncthreads();
    }
    if (tidx == 0) start[n] = carry;
}

__global__ void scatter_kernel(const int* __restrict__ src, const int* __restrict__ dst,
                               int* __restrict__ cursor, int* __restrict__ ssrc, int E)
{
    int i = blockIdx.x * blockDim.x + threadIdx.x;
    if (i < E) {
        int p = atomicAdd(&cursor[dst[i]], 1);
        ssrc[p] = src[i];
    }
}

// ======================= accumulate relu'd activations per node =======================
// T[n] = relu(A[n]+B[n]) + sum_{e in CSR[n]} relu(A[n] + B[ssrc[e]])
__global__ void __launch_bounds__(512)
accum_kernel(const float* __restrict__ A, const float* __restrict__ B,
             const int* __restrict__ ssrc, const int* __restrict__ start,
             float* __restrict__ T, int n)
{
    const int gw   = (blockIdx.x * blockDim.x + threadIdx.x) >> 5;
    const int lane = threadIdx.x & 31;
    const int nw   = (gridDim.x * blockDim.x) >> 5;

    for (int node = gw; node < n; node += nw) {
        float4 a = ((const float4*)(A + (size_t)node * 128))[lane];
        float4 bs = ((const float4*)(B + (size_t)node * 128))[lane];
        float4 acc = relu4(make_float4(a.x + bs.x, a.y + bs.y, a.z + bs.z, a.w + bs.w)); // self loop

        int e  = __ldg(start + node);
        int e1 = __ldg(start + node + 1);
        for (; e + 4 <= e1; e += 4) {
            int j0 = __ldg(ssrc + e), j1 = __ldg(ssrc + e + 1);
            int j2 = __ldg(ssrc + e + 2), j3 = __ldg(ssrc + e + 3);
            float4 b0 = ((const float4*)(B + (size_t)j0 * 128))[lane];
            float4 b1 = ((const float4*)(B + (size_t)j1 * 128))[lane];
            float4 b2 = ((const float4*)(B + (size_t)j2 * 128))[lane];
            float4 b3 = ((const float4*)(B + (size_t)j3 * 128))[lane];
            float4 t0 = relu4(make_float4(a.x + b0.x, a.y + b0.y, a.z + b0.z, a.w + b0.w));
            float4 t1 = relu4(make_float4(a.x + b1.x, a.y + b1.y, a.z + b1.z, a.w + b1.w));
            float4 t2 = relu4(make_float4(a.x + b2.x, a.y + b2.y, a.z + b2.z, a.w + b2.w));
            float4 t3 = relu4(make_float4(a.x + b3.x, a.y + b3.y, a.z + b3.z, a.w + b3.w));
            acc.x += t0.x + t1.x + t2.x + t3.x;
            acc.y += t0.y + t1.y + t2.y + t3.y;
            acc.z += t0.z + t1.z + t2.z + t3.z;
            acc.w += t0.w + t1.w + t2.w + t3.w;
        }
        for (; e < e1; e++) {
            int j = __ldg(ssrc + e);
            float4 b = ((const float4*)(B + (size_t)j * 128))[lane];
            float4 t = relu4(make_float4(a.x + b.x, a.y + b.y, a.z + b.z, a.w + b.w));
            acc.x += t.x; acc.y += t.y; acc.z += t.z; acc.w += t.w;
        }
        ((float4*)(T + (size_t)node * 128))[lane] = acc;
    }
}

// ======================= pool / final =======================
__global__ void pool_kernel(const float* __restrict__ agg, const int* __restrict__ batch,
                            float* __restrict__ pool, float* __restrict__ cnt, int n)
{
    int gw   = (blockIdx.x * blockDim.x + threadIdx.x) >> 5;
    int lane = threadIdx.x & 31;
    int nw   = (gridDim.x * blockDim.x) >> 5;
    for (int node = gw; node < n; node += nw) {
        int g = batch[node];
        float4 v = relu4(((const float4*)(agg + (size_t)node * 128))[lane]);
        float* p = pool + (size_t)g * 128 + lane * 4;
        atomicAdd(p + 0, v.x); atomicAdd(p + 1, v.y);
        atomicAdd(p + 2, v.z); atomicAdd(p + 3, v.w);
        if (lane == 0) atomicAdd(&cnt[g], 1.f);
    }
}

__global__ void final_kernel(const float* __restrict__ pool, const float* __restrict__ cnt,
                             const float* __restrict__ W, const float* __restrict__ b,
                             float* __restrict__ out)
{
    __shared__ float p[128];
    int g = blockIdx.x;
    float c = fmaxf(cnt[g], 1.f);
    for (int j = threadIdx.x; j < 128; j += blockDim.x)
        p[j] = pool[(size_t)g * 128 + j] / c;
    __syncthreads();
    int o = threadIdx.x;
    float s = b[o];
    #pragma unroll 4
    for (int j = 0; j < 128; j++) s += p[j] * W[j * 64 + o];
    out[(size_t)g * 64 + o] = s;
}

// ======================= launch =======================
extern "C" void kernel_launch(void* const* d_in, const int* in_sizes, int n_in,
                              void* d_out, int out_size)
{
    const float* x     = (const float*)d_in[0];
    const int*   ei    = (const int*)  d_in[1];
    const int*   batch = (const int*)  d_in[3];
    const int N = in_sizes[0] / 128;
    const int E = in_sizes[1] / 2;
    const int* src = ei;
    const int* dst = ei + E;

    const float* lin_w[3] = { (const float*)d_in[4],  (const float*)d_in[10], (const float*)d_in[16] };
    const float* lin_b[3] = { (const float*)d_in[5],  (const float*)d_in[11], (const float*)d_in[17] };
    const float* w1[3]    = { (const float*)d_in[6],  (const float*)d_in[12], (const float*)d_in[18] };
    const float* b1[3]    = { (const float*)d_in[7],  (const float*)d_in[13], (const float*)d_in[19] };
    const float* w2[3]    = { (const float*)d_in[8],  (const float*)d_in[14], (const float*)d_in[20] };
    const float* b2[3]    = { (const float*)d_in[9],  (const float*)d_in[15], (const float*)d_in[21] };
    const float* out_w    = (const float*)d_in[22];
    const float* out_b    = (const float*)d_in[23];
    float* out = (float*)d_out;

    float *h_, *A_, *B_, *T_, *agg_, *pool_, *cnt_;
    int *deg_, *start_, *cursor_, *ssrc_;
    cudaGetSymbolAddress((void**)&h_,     g_h);
    cudaGetSymbolAddress((void**)&A_,     g_A);
    cudaGetSymbolAddress((void**)&B_,     g_B);
    cudaGetSymbolAddress((void**)&T_,     g_T);
    cudaGetSymbolAddress((void**)&agg_,   g_agg);
    cudaGetSymbolAddress((void**)&pool_,  g_pool);
    cudaGetSymbolAddress((void**)&cnt_,   g_cnt);
    cudaGetSymbolAddress((void**)&deg_,   g_deg);
    cudaGetSymbolAddress((void**)&start_, g_start);
    cudaGetSymbolAddress((void**)&cursor_,g_cursor);
    cudaGetSymbolAddress((void**)&ssrc_,  g_ssrc);

    cudaFuncSetAttribute((const void*)node_mma_kernel<false, false>,
                         cudaFuncAttributeMaxDynamicSharedMemorySize, MMA_SMEM);
    cudaFuncSetAttribute((const void*)node_mma_kernel<true, false>,
                         cudaFuncAttributeMaxDynamicSharedMemorySize, MMA_SMEM);
    cudaFuncSetAttribute((const void*)node_mma_kernel<false, true>,
                         cudaFuncAttributeMaxDynamicSharedMemorySize, MMA_SMEM);

    const int G = out_size / 64;

    // ---- CSR by dst (once per launch) ----
    cudaMemsetAsync(deg_, 0, (size_t)N * sizeof(int));
    deg_kernel<<<(E + 255) / 256, 256>>>(dst, deg_, E);
    scan_kernel<<<1, 1024>>>(deg_, start_, cursor_, N);
    scatter_kernel<<<(E + 255) / 256, 256>>>(src, dst, cursor_, ssrc_, E);

    for (int l = 0; l < 3; l++) {
        const float* X = (l == 0) ? x : agg_;
        if (l == 0)
            node_mma_kernel<false, false><<<NBLK, TPB_E, MMA_SMEM>>>(X, lin_w[l], lin_b[l], nullptr, h_, N);
        else
            node_mma_kernel<true,  false><<<NBLK, TPB_E, MMA_SMEM>>>(X, lin_w[l], lin_b[l], nullptr, h_, N);
        node_mma_kernel<false, false><<<NBLK, TPB_E, MMA_SMEM>>>(h_, w1[l],             b1[l],  nullptr, A_, N);
        node_mma_kernel<false, false><<<NBLK, TPB_E, MMA_SMEM>>>(h_, w1[l] + 128 * 128, nullptr, nullptr, B_, N);
        accum_kernel<<<296, 512>>>(A_, B_, ssrc_, start_, T_, N);
        node_mma_kernel<false, true ><<<NBLK, TPB_E, MMA_SMEM>>>(T_, w2[l], b2[l], deg_, agg_, N);
    }

    cudaMemsetAsync(pool_, 0, (size_t)G * 128 * sizeof(float));
    cudaMemsetAsync(cnt_,  0, (size_t)G * sizeof(float));
    pool_kernel<<<256, 256>>>(agg_, batch, pool_, cnt_, N);
    final_kernel<<<G, 64>>>(pool_, cnt_, out_w, out_b, out);
}